// round 7
// baseline (speedup 1.0000x reference)
#include <cuda_runtime.h>
#include <math.h>
#include <stdint.h>

#define B_   32
#define T_   512
#define E_   256
#define H_   512
#define NG   2048
#define NBLK 128

typedef unsigned long long u64;

__device__ __align__(16) float  g_xWx  [(size_t)T_ * B_ * NG];
__device__ __align__(16) float  g_fcore[(size_t)T_ * B_ * 192];
__device__ __align__(16) float  g_revxw[(size_t)T_ * B_ * 40];
__device__ __align__(16) float2 g_d    [T_ * B_];
__device__ __align__(16) float  g_h    [2][B_ * H_];
__device__ unsigned g_cnt;
__device__ unsigned g_gen;

__device__ __forceinline__ float sigf(float x) { return 1.f / (1.f + expf(-x)); }

// ---- packed f32x2 helpers (FFMA2 path; ptxas never emits these from C++) ----
__device__ __forceinline__ u64 ffma2(u64 a, u64 b, u64 c) {
    u64 d;
    asm("fma.rn.f32x2 %0, %1, %2, %3;" : "=l"(d) : "l"(a), "l"(b), "l"(c));
    return d;
}
__device__ __forceinline__ u64 dup2(float x) {
    u64 r; asm("mov.b64 %0, {%1, %1};" : "=l"(r) : "f"(x)); return r;
}
__device__ __forceinline__ u64 pack2(float lo, float hi) {
    u64 r; asm("mov.b64 %0, {%1, %2};" : "=l"(r) : "f"(lo), "f"(hi)); return r;
}
__device__ __forceinline__ float2 lohi(u64 v) {
    float2 r; asm("mov.b64 {%0, %1}, %2;" : "=f"(r.x), "=f"(r.y) : "l"(v)); return r;
}

// ------------------- init: zero h, reset barrier -------------------
__global__ void k_init() {
    int i = blockIdx.x * blockDim.x + threadIdx.x;
    if (i < B_ * H_) g_h[0][i] = 0.f;
    if (i == 0) { g_cnt = 0; *(volatile unsigned*)&g_gen = 0u; }
}

// ------------------- xWx GEMM: M=16384 N=2048 K=256 (FFMA2) -------------------
__global__ void __launch_bounds__(256) k_xwx(const float* __restrict__ x,
                                             const float* __restrict__ Wx,
                                             const float* __restrict__ bias)
{
    __shared__ __align__(16) float a_sh[8][128];
    __shared__ __align__(16) float b_sh[8][128];
    const int n0 = blockIdx.x * 128;
    const int m0 = blockIdx.y * 128;
    const int tid = threadIdx.x;
    const int ty8 = (tid >> 4) * 8;
    const int tx8 = (tid & 15) * 8;

    u64 acc[8][4];
#pragma unroll
    for (int i = 0; i < 8; ++i)
#pragma unroll
        for (int j = 0; j < 4; ++j) acc[i][j] = 0ull;

    const int arow = tid >> 1;
    const int akq  = (tid & 1) * 4;
    const int m    = m0 + arow;
    const int bb   = m & 31;
    const int tt   = m >> 5;
    const float* aptr = x + ((size_t)bb * T_ + tt) * E_ + akq;
    const int bkk = tid >> 5;
    const int bnq = (tid & 31) * 4;

    for (int k0 = 0; k0 < E_; k0 += 8) {
        float4 av = *(const float4*)(aptr + k0);
        a_sh[akq + 0][arow] = av.x;
        a_sh[akq + 1][arow] = av.y;
        a_sh[akq + 2][arow] = av.z;
        a_sh[akq + 3][arow] = av.w;
        *(float4*)&b_sh[bkk][bnq] = *(const float4*)(Wx + (size_t)(k0 + bkk) * NG + n0 + bnq);
        __syncthreads();
#pragma unroll
        for (int k = 0; k < 8; ++k) {
            float af[8];
            *(float4*)(af)     = *(const float4*)&a_sh[k][ty8];
            *(float4*)(af + 4) = *(const float4*)&a_sh[k][ty8 + 4];
            ulonglong2 b01 = *(const ulonglong2*)&b_sh[k][tx8];
            ulonglong2 b23 = *(const ulonglong2*)&b_sh[k][tx8 + 4];
            u64 bp0 = b01.x, bp1 = b01.y, bp2 = b23.x, bp3 = b23.y;
#pragma unroll
            for (int i = 0; i < 8; ++i) {
                u64 ai = dup2(af[i]);
                acc[i][0] = ffma2(ai, bp0, acc[i][0]);
                acc[i][1] = ffma2(ai, bp1, acc[i][1]);
                acc[i][2] = ffma2(ai, bp2, acc[i][2]);
                acc[i][3] = ffma2(ai, bp3, acc[i][3]);
            }
        }
        __syncthreads();
    }
    float bsv[8];
    *(float4*)(bsv)     = *(const float4*)(bias + n0 + tx8);
    *(float4*)(bsv + 4) = *(const float4*)(bias + n0 + tx8 + 4);
#pragma unroll
    for (int i = 0; i < 8; ++i) {
        float* cp = g_xWx + (size_t)(m0 + ty8 + i) * NG + n0 + tx8;
        float2 p0 = lohi(acc[i][0]), p1 = lohi(acc[i][1]);
        float2 p2 = lohi(acc[i][2]), p3 = lohi(acc[i][3]);
        *(float4*)cp       = make_float4(p0.x + bsv[0], p0.y + bsv[1], p1.x + bsv[2], p1.y + bsv[3]);
        *(float4*)(cp + 4) = make_float4(p2.x + bsv[4], p2.y + bsv[5], p3.x + bsv[6], p3.y + bsv[7]);
    }
}

// ------------------- convs -> g_fcore[..][0..180), 16 timesteps/block -------------------
__global__ void __launch_bounds__(720) k_conv(const float* __restrict__ x,
        const float* __restrict__ w1, const float* __restrict__ b1,
        const float* __restrict__ w2, const float* __restrict__ b2,
        const float* __restrict__ w3, const float* __restrict__ b3)
{
    __shared__ float xs[20][256];
    const int t0 = blockIdx.x * 16;
    const int b  = blockIdx.y;
    const int tid = threadIdx.x;

    for (int i = tid; i < 20 * 256; i += 720) {
        int r = i >> 8, e = i & 255;
        int t = t0 - 2 + r;
        xs[r][e] = (t >= 0 && t < T_) ? x[((size_t)b * T_ + t) * E_ + e] : 0.f;
    }
    __syncthreads();

    const int tloc = tid / 45;
    const int grp  = tid % 45;
    const float* w; const float* bias; int K, pl, cbase, c4;
    if (grp < 15)      { w = w1; bias = b1; K = 3; pl = 1; cbase = 0;   c4 = grp * 4; }
    else if (grp < 30) { w = w2; bias = b2; K = 4; pl = 1; cbase = 60;  c4 = (grp - 15) * 4; }
    else               { w = w3; bias = b3; K = 5; pl = 2; cbase = 120; c4 = (grp - 30) * 4; }

    u64 a01 = pack2(bias[c4],     bias[c4 + 1]);
    u64 a23 = pack2(bias[c4 + 2], bias[c4 + 3]);
    for (int dt = 0; dt < K; ++dt) {
        const int r = tloc + dt - pl + 2;
        const float* wp = w + (size_t)dt * E_ * 60 + c4;
#pragma unroll 4
        for (int e = 0; e < E_; ++e) {
            u64 xd = dup2(xs[r][e]);
            ulonglong2 wv = *(const ulonglong2*)(wp + (size_t)e * 60);
            a01 = ffma2(xd, wv.x, a01);
            a23 = ffma2(xd, wv.y, a23);
        }
    }
    const int t = t0 + tloc;
    float2 p0 = lohi(a01), p1 = lohi(a23);
    *(float4*)&g_fcore[((size_t)t * B_ + b) * 192 + cbase + c4] =
        make_float4(p0.x, p0.y, p1.x, p1.y);
}

// ------------------- rev-LSTM input projection -------------------
__global__ void __launch_bounds__(320) k_revxw(const float* __restrict__ x,
                                               const float* __restrict__ Wx)
{
    __shared__ float xr[32][256];
    const int s = blockIdx.x, tid = threadIdx.x;
    const int t = T_ - 1 - s;
    for (int i = tid; i < 32 * 256; i += 320) {
        int b = i >> 8, e = i & 255;
        xr[b][e] = x[((size_t)b * T_ + t) * E_ + e];
    }
    __syncthreads();
    const int b = tid / 10, j = tid % 10;
    float a0 = 0.f, a1 = 0.f, a2 = 0.f, a3 = 0.f;
#pragma unroll 4
    for (int e = 0; e < 256; ++e) {
        float xv = xr[b][e];
        const float* wp = Wx + (size_t)e * 40 + j;
        a0 = fmaf(xv, __ldg(wp),      a0);
        a1 = fmaf(xv, __ldg(wp + 10), a1);
        a2 = fmaf(xv, __ldg(wp + 20), a2);
        a3 = fmaf(xv, __ldg(wp + 30), a3);
    }
    float* dst = &g_revxw[((size_t)s * B_ + b) * 40 + j];
    dst[0] = a0; dst[10] = a1; dst[20] = a2; dst[30] = a3;
}

// ------------------- rev-LSTM scan (single block) -------------------
__global__ void __launch_bounds__(320) k_revscan(const float* __restrict__ Wh,
                                                 const float* __restrict__ bias)
{
    __shared__ float h[320];
    __shared__ float wsh[400];
    const int tid = threadIdx.x;
    for (int i = tid; i < 400; i += 320) wsh[i] = Wh[i];
    h[tid] = 0.f;
    const int b = tid / 10, j = tid % 10;
    const float bi = bias[j], bf = bias[10 + j], bg = bias[20 + j], bo = bias[30 + j];
    float c = 0.f;
    __syncthreads();
    for (int s = 0; s < T_; ++s) {
        const float* zx = &g_revxw[((size_t)s * B_ + b) * 40];
        float zi = zx[j] + bi, zf = zx[10 + j] + bf, zg = zx[20 + j] + bg, zo = zx[30 + j] + bo;
#pragma unroll
        for (int p = 0; p < 10; ++p) {
            float hv = h[b * 10 + p];
            zi = fmaf(hv, wsh[p * 40 + j],      zi);
            zf = fmaf(hv, wsh[p * 40 + 10 + j], zf);
            zg = fmaf(hv, wsh[p * 40 + 20 + j], zg);
            zo = fmaf(hv, wsh[p * 40 + 30 + j], zo);
        }
        c = sigf(zf) * c + sigf(zi) * tanhf(zg);
        float hn = sigf(zo) * tanhf(c);
        __syncthreads();
        h[tid] = hn;
        g_fcore[((size_t)s * B_ + b) * 192 + 180 + j] = hn;
        __syncthreads();
    }
}

// ------------------- gate MLP -> g_d (8 pairs per block) -------------------
__global__ void __launch_bounds__(128) k_gate(const float* __restrict__ x,
        const float* __restrict__ d0W, const float* __restrict__ d0b,
        const float* __restrict__ d1W, const float* __restrict__ d1b,
        const float* __restrict__ gn)
{
    __shared__ float in_sh[8][448];
    __shared__ float hid_sh[8][100];
    const int q0 = blockIdx.x * 8;
    const int tid = threadIdx.x;
    for (int i = tid; i < 8 * 448; i += 128) {
        int u = i / 448, e = i % 448;
        int q = q0 + u, t = q >> 5, b = q & 31;
        float v = 0.f;
        if (e < 190) { if (t < T_ - 1) v = g_fcore[((size_t)(t + 1) * B_ + b) * 192 + e]; }
        else if (e < 446) v = x[((size_t)b * T_ + t) * E_ + (e - 190)];
        in_sh[u][e] = v;
    }
    __syncthreads();
    if (tid < 100) {
        float acc[8];
#pragma unroll
        for (int u = 0; u < 8; ++u) acc[u] = d0b[tid];
        for (int e = 0; e < 446; ++e) {
            float w = d0W[(size_t)e * 100 + tid];
#pragma unroll
            for (int u = 0; u < 8; ++u) acc[u] = fmaf(in_sh[u][e], w, acc[u]);
        }
#pragma unroll
        for (int u = 0; u < 8; ++u) hid_sh[u][tid] = fmaxf(acc[u], 0.f);
    }
    __syncthreads();
    if (tid < 8) {
        const int u = tid, q = q0 + u, t = q >> 5, b = q & 31;
        float p0 = d1b[0], p1 = d1b[1];
        for (int j = 0; j < 100; ++j) {
            float hv = hid_sh[u][j];
            p0 = fmaf(hv, d1W[2 * j],     p0);
            p1 = fmaf(hv, d1W[2 * j + 1], p1);
        }
        float a0 = (p0 + gn[((size_t)t * B_ + b) * 2])     / 1e-5f;
        float a1 = (p1 + gn[((size_t)t * B_ + b) * 2 + 1]) / 1e-5f;
        float mx = fmaxf(a0, a1);
        float e0 = expf(a0 - mx), e1 = expf(a1 - mx);
        float s = e0 + e1;
        g_d[q] = make_float2(e0 / s, e1 / s);
    }
}

// ------------------- main persistent scan (FFMA2, 8b x 8c warps) -------------------
__global__ void __launch_bounds__(256, 1) k_scan(const float* __restrict__ Wh,
                                                 float* __restrict__ out)
{
    extern __shared__ float sm[];
    float* w_sh = sm;                 // [16][512]
    float* h_sh = sm + 16 * 512;      // [32][512]
    float* z_sh = h_sh + 32 * 512;    // [32][16]
    const int tid  = threadIdx.x;
    const int nb   = blockIdx.x;
    const int wid  = tid >> 5;
    const int lane = tid & 31;
    // warp covers 8 batches x 8 cols; lane tile 4b x 4c x 8-way k-split
    const int bbase = ((wid & 3) << 3) + ((lane >> 4) << 2);
    const int cbase = ((wid >> 2) << 3) + (((lane >> 3) & 1) << 2);
    const int ks    = lane & 7;

    // load 16 Wh columns (col c: gate=c>>2, hh=c&3, n = gate*512 + nb*4 + hh)
    for (int idx = tid; idx < 16 * 512; idx += 256) {
        int c = idx >> 9, k = idx & 511;
        int n = (c >> 2) * 512 + nb * 4 + (c & 3);
        w_sh[c * 512 + k] = Wh[(size_t)k * NG + n];
    }

    const int cb = tid >> 2;          // combine thread batch (tid<128)
    const int hh = tid & 3;
    const int hglob = nb * 4 + hh;
    float cst = 0.f;

    const float* hp = h_sh + bbase * 512 + ks * 4;
    const float* wp = w_sh + cbase * 512 + ks * 4;

    for (int t = 0; t < T_; ++t) {
        const int cur = t & 1;
        const float* hg = g_h[cur];
        for (int i = tid; i < (B_ * H_) / 4; i += 256)
            ((float4*)h_sh)[i] = __ldcg(((const float4*)hg) + i);

        float4 zx; float2 dv;
        if (tid < 128) {
            const float* xw = g_xWx + ((size_t)t * B_ + cb) * NG + hglob;
            zx.x = __ldg(xw);
            zx.y = __ldg(xw + 512);
            zx.z = __ldg(xw + 1024);
            zx.w = __ldg(xw + 1536);
            dv = g_d[t * B_ + cb];
        }
        __syncthreads();

        u64 acc[4][4];
#pragma unroll
        for (int i = 0; i < 4; ++i)
#pragma unroll
            for (int j = 0; j < 4; ++j) acc[i][j] = 0ull;

#pragma unroll 4
        for (int it = 0; it < 16; ++it) {
            const int ko = it * 32;
            ulonglong2 hv[4], wv[4];
#pragma unroll
            for (int bi = 0; bi < 4; ++bi) hv[bi] = *(const ulonglong2*)(hp + bi * 512 + ko);
#pragma unroll
            for (int ci = 0; ci < 4; ++ci) wv[ci] = *(const ulonglong2*)(wp + ci * 512 + ko);
#pragma unroll
            for (int bi = 0; bi < 4; ++bi)
#pragma unroll
                for (int ci = 0; ci < 4; ++ci) {
                    acc[bi][ci] = ffma2(hv[bi].x, wv[ci].x, acc[bi][ci]);
                    acc[bi][ci] = ffma2(hv[bi].y, wv[ci].y, acc[bi][ci]);
                }
        }
        float r[4][4];
#pragma unroll
        for (int bi = 0; bi < 4; ++bi)
#pragma unroll
            for (int ci = 0; ci < 4; ++ci) {
                float2 p = lohi(acc[bi][ci]);
                r[bi][ci] = p.x + p.y;
            }
#pragma unroll
        for (int off = 4; off; off >>= 1)
#pragma unroll
            for (int bi = 0; bi < 4; ++bi)
#pragma unroll
                for (int ci = 0; ci < 4; ++ci)
                    r[bi][ci] += __shfl_xor_sync(0xffffffffu, r[bi][ci], off);
        if (ks == 0) {
#pragma unroll
            for (int bi = 0; bi < 4; ++bi)
#pragma unroll
                for (int ci = 0; ci < 4; ++ci)
                    z_sh[(bbase + bi) * 16 + cbase + ci] = r[bi][ci];
        }
        __syncthreads();

        if (tid < 128) {
            float zi = z_sh[cb * 16 + 0  + hh] + zx.x;
            float zf = z_sh[cb * 16 + 4  + hh] + zx.y;
            float zg = z_sh[cb * 16 + 8  + hh] + zx.z;
            float zo = z_sh[cb * 16 + 12 + hh] + zx.w;
            float ccand = sigf(zf) * cst + sigf(zi) * tanhf(zg);
            float hcand = sigf(zo) * tanhf(ccand);
            out[(size_t)cb * (T_ * H_) + (size_t)t * H_ + hglob] = hcand;
            float hold = h_sh[cb * 512 + hglob];
            float hnew = dv.x * hcand + dv.y * hold;
            cst = dv.x * ccand + dv.y * cst;
            g_h[1 - cur][cb * 512 + hglob] = hnew;
        }
        __syncthreads();
        if (tid == 0) {
            __threadfence();
            unsigned a = atomicAdd(&g_cnt, 1u);
            if (a == NBLK - 1) {
                g_cnt = 0;
                __threadfence();
                *(volatile unsigned*)&g_gen = (unsigned)(t + 1);
            } else {
                while (*(volatile unsigned*)&g_gen < (unsigned)(t + 1)) __nanosleep(16);
                __threadfence();
            }
        }
        __syncthreads();
    }
}

extern "C" void kernel_launch(void* const* d_in, const int* in_sizes, int n_in,
                              void* d_out, int out_size) {
    const float* x   = (const float*)d_in[0];
    const float* c1w = (const float*)d_in[1];
    const float* c1b = (const float*)d_in[2];
    const float* c2w = (const float*)d_in[3];
    const float* c2b = (const float*)d_in[4];
    const float* c3w = (const float*)d_in[5];
    const float* c3b = (const float*)d_in[6];
    const float* rWx = (const float*)d_in[7];
    const float* rWh = (const float*)d_in[8];
    const float* rb  = (const float*)d_in[9];
    const float* d0W = (const float*)d_in[10];
    const float* d0b = (const float*)d_in[11];
    const float* d1W = (const float*)d_in[12];
    const float* d1b = (const float*)d_in[13];
    const float* cWx = (const float*)d_in[14];
    const float* cWh = (const float*)d_in[15];
    const float* cb  = (const float*)d_in[16];
    const float* gn  = (const float*)d_in[17];
    float* out = (float*)d_out;

    static int smem_set = 0;
    const int SMEM = (16 * 512 + 32 * 512 + 32 * 16) * 4;
    if (!smem_set) {
        cudaFuncSetAttribute(k_scan, cudaFuncAttributeMaxDynamicSharedMemorySize, SMEM);
        smem_set = 1;
    }

    k_init<<<32, 512>>>();
    k_xwx<<<dim3(16, 128), 256>>>(x, cWx, cb);
    k_conv<<<dim3(T_ / 16, B_), 720>>>(x, c1w, c1b, c2w, c2b, c3w, c3b);
    k_revxw<<<T_, 320>>>(x, rWx);
    k_revscan<<<1, 320>>>(rWh, rb);
    k_gate<<<(T_ * B_) / 8, 128>>>(x, d0W, d0b, d1W, d1b, gn);
    k_scan<<<NBLK, 256, SMEM>>>(cWh, out);
}

// round 8
// speedup vs baseline: 1.0097x; 1.0097x over previous
#include <cuda_runtime.h>
#include <math.h>
#include <stdint.h>

#define B_   32
#define T_   512
#define E_   256
#define H_   512
#define NG   2048
#define NBLK 128

typedef unsigned long long u64;

__device__ __align__(16) float  g_xWx  [(size_t)T_ * B_ * NG];
__device__ __align__(16) float  g_fcore[(size_t)T_ * B_ * 192];
__device__ __align__(16) float  g_revxw[(size_t)T_ * B_ * 40];
__device__ __align__(16) float2 g_d    [T_ * B_];
__device__ __align__(16) float  g_h    [2][B_ * H_];
__device__ unsigned g_cnt;
__device__ unsigned g_gen;

__device__ __forceinline__ float sigf(float x) { return 1.f / (1.f + expf(-x)); }

// ---- packed f32x2 helpers ----
__device__ __forceinline__ u64 ffma2(u64 a, u64 b, u64 c) {
    u64 d;
    asm("fma.rn.f32x2 %0, %1, %2, %3;" : "=l"(d) : "l"(a), "l"(b), "l"(c));
    return d;
}
__device__ __forceinline__ u64 dup2(float x) {
    u64 r; asm("mov.b64 %0, {%1, %1};" : "=l"(r) : "f"(x)); return r;
}
__device__ __forceinline__ u64 pack2(float lo, float hi) {
    u64 r; asm("mov.b64 %0, {%1, %2};" : "=l"(r) : "f"(lo), "f"(hi)); return r;
}
__device__ __forceinline__ float2 lohi(u64 v) {
    float2 r; asm("mov.b64 {%0, %1}, %2;" : "=f"(r.x), "=f"(r.y) : "l"(v)); return r;
}

// ---- release/acquire primitives for grid barrier ----
__device__ __forceinline__ unsigned atom_add_release(unsigned* p, unsigned v) {
    unsigned old;
    asm volatile("atom.release.gpu.global.add.u32 %0, [%1], %2;"
                 : "=r"(old) : "l"(p), "r"(v) : "memory");
    return old;
}
__device__ __forceinline__ void st_release(unsigned* p, unsigned v) {
    asm volatile("st.release.gpu.global.u32 [%0], %1;" :: "l"(p), "r"(v) : "memory");
}
__device__ __forceinline__ unsigned ld_acquire(const unsigned* p) {
    unsigned v;
    asm volatile("ld.acquire.gpu.global.u32 %0, [%1];" : "=r"(v) : "l"(p) : "memory");
    return v;
}

// ------------------- init -------------------
__global__ void k_init() {
    int i = blockIdx.x * blockDim.x + threadIdx.x;
    if (i < B_ * H_) g_h[0][i] = 0.f;
    if (i == 0) { g_cnt = 0; g_gen = 0u; }
}

// ------------------- xWx GEMM: M=16384 N=2048 K=256 (FFMA2) -------------------
__global__ void __launch_bounds__(256) k_xwx(const float* __restrict__ x,
                                             const float* __restrict__ Wx,
                                             const float* __restrict__ bias)
{
    __shared__ __align__(16) float a_sh[8][128];
    __shared__ __align__(16) float b_sh[8][128];
    const int n0 = blockIdx.x * 128;
    const int m0 = blockIdx.y * 128;
    const int tid = threadIdx.x;
    const int ty8 = (tid >> 4) * 8;
    const int tx8 = (tid & 15) * 8;

    u64 acc[8][4];
#pragma unroll
    for (int i = 0; i < 8; ++i)
#pragma unroll
        for (int j = 0; j < 4; ++j) acc[i][j] = 0ull;

    const int arow = tid >> 1;
    const int akq  = (tid & 1) * 4;
    const int m    = m0 + arow;
    const int bb   = m & 31;
    const int tt   = m >> 5;
    const float* aptr = x + ((size_t)bb * T_ + tt) * E_ + akq;
    const int bkk = tid >> 5;
    const int bnq = (tid & 31) * 4;

    for (int k0 = 0; k0 < E_; k0 += 8) {
        float4 av = *(const float4*)(aptr + k0);
        a_sh[akq + 0][arow] = av.x;
        a_sh[akq + 1][arow] = av.y;
        a_sh[akq + 2][arow] = av.z;
        a_sh[akq + 3][arow] = av.w;
        *(float4*)&b_sh[bkk][bnq] = *(const float4*)(Wx + (size_t)(k0 + bkk) * NG + n0 + bnq);
        __syncthreads();
#pragma unroll
        for (int k = 0; k < 8; ++k) {
            float af[8];
            *(float4*)(af)     = *(const float4*)&a_sh[k][ty8];
            *(float4*)(af + 4) = *(const float4*)&a_sh[k][ty8 + 4];
            ulonglong2 b01 = *(const ulonglong2*)&b_sh[k][tx8];
            ulonglong2 b23 = *(const ulonglong2*)&b_sh[k][tx8 + 4];
#pragma unroll
            for (int i = 0; i < 8; ++i) {
                u64 ai = dup2(af[i]);
                acc[i][0] = ffma2(ai, b01.x, acc[i][0]);
                acc[i][1] = ffma2(ai, b01.y, acc[i][1]);
                acc[i][2] = ffma2(ai, b23.x, acc[i][2]);
                acc[i][3] = ffma2(ai, b23.y, acc[i][3]);
            }
        }
        __syncthreads();
    }
    float bsv[8];
    *(float4*)(bsv)     = *(const float4*)(bias + n0 + tx8);
    *(float4*)(bsv + 4) = *(const float4*)(bias + n0 + tx8 + 4);
#pragma unroll
    for (int i = 0; i < 8; ++i) {
        float* cp = g_xWx + (size_t)(m0 + ty8 + i) * NG + n0 + tx8;
        float2 p0 = lohi(acc[i][0]), p1 = lohi(acc[i][1]);
        float2 p2 = lohi(acc[i][2]), p3 = lohi(acc[i][3]);
        *(float4*)cp       = make_float4(p0.x + bsv[0], p0.y + bsv[1], p1.x + bsv[2], p1.y + bsv[3]);
        *(float4*)(cp + 4) = make_float4(p2.x + bsv[4], p2.y + bsv[5], p3.x + bsv[6], p3.y + bsv[7]);
    }
}

// ------------------- convs -------------------
__global__ void __launch_bounds__(720) k_conv(const float* __restrict__ x,
        const float* __restrict__ w1, const float* __restrict__ b1,
        const float* __restrict__ w2, const float* __restrict__ b2,
        const float* __restrict__ w3, const float* __restrict__ b3)
{
    __shared__ float xs[20][256];
    const int t0 = blockIdx.x * 16;
    const int b  = blockIdx.y;
    const int tid = threadIdx.x;

    for (int i = tid; i < 20 * 256; i += 720) {
        int r = i >> 8, e = i & 255;
        int t = t0 - 2 + r;
        xs[r][e] = (t >= 0 && t < T_) ? x[((size_t)b * T_ + t) * E_ + e] : 0.f;
    }
    __syncthreads();

    const int tloc = tid / 45;
    const int grp  = tid % 45;
    const float* w; const float* bias; int K, pl, cbase, c4;
    if (grp < 15)      { w = w1; bias = b1; K = 3; pl = 1; cbase = 0;   c4 = grp * 4; }
    else if (grp < 30) { w = w2; bias = b2; K = 4; pl = 1; cbase = 60;  c4 = (grp - 15) * 4; }
    else               { w = w3; bias = b3; K = 5; pl = 2; cbase = 120; c4 = (grp - 30) * 4; }

    u64 a01 = pack2(bias[c4],     bias[c4 + 1]);
    u64 a23 = pack2(bias[c4 + 2], bias[c4 + 3]);
    for (int dt = 0; dt < K; ++dt) {
        const int r = tloc + dt - pl + 2;
        const float* wp = w + (size_t)dt * E_ * 60 + c4;
#pragma unroll 4
        for (int e = 0; e < E_; ++e) {
            u64 xd = dup2(xs[r][e]);
            ulonglong2 wv = *(const ulonglong2*)(wp + (size_t)e * 60);
            a01 = ffma2(xd, wv.x, a01);
            a23 = ffma2(xd, wv.y, a23);
        }
    }
    const int t = t0 + tloc;
    float2 p0 = lohi(a01), p1 = lohi(a23);
    *(float4*)&g_fcore[((size_t)t * B_ + b) * 192 + cbase + c4] =
        make_float4(p0.x, p0.y, p1.x, p1.y);
}

// ------------------- rev-LSTM input projection -------------------
__global__ void __launch_bounds__(320) k_revxw(const float* __restrict__ x,
                                               const float* __restrict__ Wx)
{
    __shared__ float xr[32][256];
    const int s = blockIdx.x, tid = threadIdx.x;
    const int t = T_ - 1 - s;
    for (int i = tid; i < 32 * 256; i += 320) {
        int b = i >> 8, e = i & 255;
        xr[b][e] = x[((size_t)b * T_ + t) * E_ + e];
    }
    __syncthreads();
    const int b = tid / 10, j = tid % 10;
    float a0 = 0.f, a1 = 0.f, a2 = 0.f, a3 = 0.f;
#pragma unroll 4
    for (int e = 0; e < 256; ++e) {
        float xv = xr[b][e];
        const float* wp = Wx + (size_t)e * 40 + j;
        a0 = fmaf(xv, __ldg(wp),      a0);
        a1 = fmaf(xv, __ldg(wp + 10), a1);
        a2 = fmaf(xv, __ldg(wp + 20), a2);
        a3 = fmaf(xv, __ldg(wp + 30), a3);
    }
    float* dst = &g_revxw[((size_t)s * B_ + b) * 40 + j];
    dst[0] = a0; dst[10] = a1; dst[20] = a2; dst[30] = a3;
}

// ------------------- rev-LSTM scan -------------------
__global__ void __launch_bounds__(320) k_revscan(const float* __restrict__ Wh,
                                                 const float* __restrict__ bias)
{
    __shared__ float h[320];
    __shared__ float wsh[400];
    const int tid = threadIdx.x;
    for (int i = tid; i < 400; i += 320) wsh[i] = Wh[i];
    h[tid] = 0.f;
    const int b = tid / 10, j = tid % 10;
    const float bi = bias[j], bf = bias[10 + j], bg = bias[20 + j], bo = bias[30 + j];
    float c = 0.f;
    __syncthreads();
    for (int s = 0; s < T_; ++s) {
        const float* zx = &g_revxw[((size_t)s * B_ + b) * 40];
        float zi = zx[j] + bi, zf = zx[10 + j] + bf, zg = zx[20 + j] + bg, zo = zx[30 + j] + bo;
#pragma unroll
        for (int p = 0; p < 10; ++p) {
            float hv = h[b * 10 + p];
            zi = fmaf(hv, wsh[p * 40 + j],      zi);
            zf = fmaf(hv, wsh[p * 40 + 10 + j], zf);
            zg = fmaf(hv, wsh[p * 40 + 20 + j], zg);
            zo = fmaf(hv, wsh[p * 40 + 30 + j], zo);
        }
        c = sigf(zf) * c + sigf(zi) * tanhf(zg);
        float hn = sigf(zo) * tanhf(c);
        __syncthreads();
        h[tid] = hn;
        g_fcore[((size_t)s * B_ + b) * 192 + 180 + j] = hn;
        __syncthreads();
    }
}

// ------------------- gate MLP -------------------
__global__ void __launch_bounds__(128) k_gate(const float* __restrict__ x,
        const float* __restrict__ d0W, const float* __restrict__ d0b,
        const float* __restrict__ d1W, const float* __restrict__ d1b,
        const float* __restrict__ gn)
{
    __shared__ float in_sh[8][448];
    __shared__ float hid_sh[8][100];
    const int q0 = blockIdx.x * 8;
    const int tid = threadIdx.x;
    for (int i = tid; i < 8 * 448; i += 128) {
        int u = i / 448, e = i % 448;
        int q = q0 + u, t = q >> 5, b = q & 31;
        float v = 0.f;
        if (e < 190) { if (t < T_ - 1) v = g_fcore[((size_t)(t + 1) * B_ + b) * 192 + e]; }
        else if (e < 446) v = x[((size_t)b * T_ + t) * E_ + (e - 190)];
        in_sh[u][e] = v;
    }
    __syncthreads();
    if (tid < 100) {
        float acc[8];
#pragma unroll
        for (int u = 0; u < 8; ++u) acc[u] = d0b[tid];
        for (int e = 0; e < 446; ++e) {
            float w = d0W[(size_t)e * 100 + tid];
#pragma unroll
            for (int u = 0; u < 8; ++u) acc[u] = fmaf(in_sh[u][e], w, acc[u]);
        }
#pragma unroll
        for (int u = 0; u < 8; ++u) hid_sh[u][tid] = fmaxf(acc[u], 0.f);
    }
    __syncthreads();
    if (tid < 8) {
        const int u = tid, q = q0 + u, t = q >> 5, b = q & 31;
        float p0 = d1b[0], p1 = d1b[1];
        for (int j = 0; j < 100; ++j) {
            float hv = hid_sh[u][j];
            p0 = fmaf(hv, d1W[2 * j],     p0);
            p1 = fmaf(hv, d1W[2 * j + 1], p1);
        }
        float a0 = (p0 + gn[((size_t)t * B_ + b) * 2])     / 1e-5f;
        float a1 = (p1 + gn[((size_t)t * B_ + b) * 2 + 1]) / 1e-5f;
        float mx = fmaxf(a0, a1);
        float e0 = expf(a0 - mx), e1 = expf(a1 - mx);
        float s = e0 + e1;
        g_d[q] = make_float2(e0 / s, e1 / s);
    }
}

// ------------------- main persistent scan: W in registers -------------------
// Block nb owns 16 output cols: n = g*512 + nb*4 + hh  (g=0..3 gate, hh=0..3).
// Lane mapping: kc = lane>>4 (k-half within warp), c_idx = lane&15.
// Lane k-range: k0 = wid*64 + kc*32, 32 k-values -> Wh slice in 16 f32x2 regs.
// Per step: loop b=0..31, half-warp broadcast-reads h_sh[b][k0..k0+31].
__global__ void __launch_bounds__(256, 1) k_scan(const float* __restrict__ Wh,
                                                 float* __restrict__ out)
{
    extern __shared__ float sm[];
    float* h_sh    = sm;               // [32][512]  64KB
    float* part_sh = sm + 32 * 512;    // [8][512]   16KB
    const int tid  = threadIdx.x;
    const int nb   = blockIdx.x;
    const int wid  = tid >> 5;
    const int lane = tid & 31;
    const int kc    = lane >> 4;
    const int c_idx = lane & 15;
    const int k0    = wid * 64 + kc * 32;
    const int ncol  = (c_idx >> 2) * 512 + nb * 4 + (c_idx & 3);

    // Wh slice into registers (once)
    u64 wreg[16];
#pragma unroll
    for (int j = 0; j < 16; ++j) {
        float w0 = __ldg(Wh + (size_t)(k0 + 2 * j)     * NG + ncol);
        float w1 = __ldg(Wh + (size_t)(k0 + 2 * j + 1) * NG + ncol);
        wreg[j] = pack2(w0, w1);
    }

    const int cb = tid >> 2;           // combine thread batch (tid<128)
    const int hh = tid & 3;
    const int hglob = nb * 4 + hh;
    float cst = 0.f;

    for (int t = 0; t < T_; ++t) {
        const int cur = t & 1;

        // per-(t,b) scalars first so their latency overlaps the h staging
        float4 zx; float2 dv;
        if (tid < 128) {
            const float* xw = g_xWx + ((size_t)t * B_ + cb) * NG + hglob;
            zx.x = __ldg(xw);
            zx.y = __ldg(xw + 512);
            zx.z = __ldg(xw + 1024);
            zx.w = __ldg(xw + 1536);
            dv = g_d[t * B_ + cb];
        }

        const float* hg = g_h[cur];
        for (int i = tid; i < (B_ * H_) / 4; i += 256)
            ((float4*)h_sh)[i] = __ldcg(((const float4*)hg) + i);
        __syncthreads();

        // ---- dot: 32 batches, 32 k each, broadcast h reads ----
        u64 acc2[32];
#pragma unroll
        for (int b = 0; b < 32; ++b) acc2[b] = 0ull;
#pragma unroll
        for (int b = 0; b < 32; ++b) {
            const ulonglong2* hp = (const ulonglong2*)(h_sh + b * 512 + k0);
            u64 a = acc2[b];
#pragma unroll
            for (int q = 0; q < 4; ++q) {
                ulonglong2 h01 = hp[2 * q];
                ulonglong2 h23 = hp[2 * q + 1];
                a = ffma2(h01.x, wreg[4 * q + 0], a);
                a = ffma2(h01.y, wreg[4 * q + 1], a);
                a = ffma2(h23.x, wreg[4 * q + 2], a);
                a = ffma2(h23.y, wreg[4 * q + 3], a);
            }
            acc2[b] = a;
        }

        // ---- reduce: collapse f32x2, one shfl stage (kc pair), smem partials ----
        float r[32];
#pragma unroll
        for (int b = 0; b < 32; ++b) {
            float2 p = lohi(acc2[b]);
            r[b] = p.x + p.y;
        }
#pragma unroll
        for (int b = 0; b < 32; ++b)
            r[b] += __shfl_xor_sync(0xffffffffu, r[b], 16);
        if (kc == 0) {
#pragma unroll
            for (int b = 0; b < 32; ++b)
                part_sh[wid * 512 + b * 16 + c_idx] = r[b];
        }
        __syncthreads();

        if (tid < 128) {
            float zg4[4];
#pragma unroll
            for (int g = 0; g < 4; ++g) {
                float s = 0.f;
#pragma unroll
                for (int w8 = 0; w8 < 8; ++w8)
                    s += part_sh[w8 * 512 + cb * 16 + g * 4 + hh];
                zg4[g] = s;
            }
            float zi = zg4[0] + zx.x;
            float zf = zg4[1] + zx.y;
            float zg = zg4[2] + zx.z;
            float zo = zg4[3] + zx.w;
            float ccand = sigf(zf) * cst + sigf(zi) * tanhf(zg);
            float hcand = sigf(zo) * tanhf(ccand);
            out[(size_t)cb * (T_ * H_) + (size_t)t * H_ + hglob] = hcand;
            float hold = h_sh[cb * 512 + hglob];
            float hnew = dv.x * hcand + dv.y * hold;
            cst = dv.x * ccand + dv.y * cst;
            g_h[1 - cur][cb * 512 + hglob] = hnew;
        }
        __syncthreads();

        // ---- release/acquire grid barrier ----
        if (tid == 0) {
            unsigned a = atom_add_release(&g_cnt, 1u);
            if (a == NBLK - 1) {
                g_cnt = 0;
                st_release(&g_gen, (unsigned)(t + 1));
            } else {
                while (ld_acquire(&g_gen) < (unsigned)(t + 1)) __nanosleep(16);
            }
        }
        __syncthreads();
    }
}

extern "C" void kernel_launch(void* const* d_in, const int* in_sizes, int n_in,
                              void* d_out, int out_size) {
    const float* x   = (const float*)d_in[0];
    const float* c1w = (const float*)d_in[1];
    const float* c1b = (const float*)d_in[2];
    const float* c2w = (const float*)d_in[3];
    const float* c2b = (const float*)d_in[4];
    const float* c3w = (const float*)d_in[5];
    const float* c3b = (const float*)d_in[6];
    const float* rWx = (const float*)d_in[7];
    const float* rWh = (const float*)d_in[8];
    const float* rb  = (const float*)d_in[9];
    const float* d0W = (const float*)d_in[10];
    const float* d0b = (const float*)d_in[11];
    const float* d1W = (const float*)d_in[12];
    const float* d1b = (const float*)d_in[13];
    const float* cWx = (const float*)d_in[14];
    const float* cWh = (const float*)d_in[15];
    const float* cb  = (const float*)d_in[16];
    const float* gn  = (const float*)d_in[17];
    float* out = (float*)d_out;

    static int smem_set = 0;
    const int SMEM = (32 * 512 + 8 * 512) * 4;   // 80 KB
    if (!smem_set) {
        cudaFuncSetAttribute(k_scan, cudaFuncAttributeMaxDynamicSharedMemorySize, SMEM);
        smem_set = 1;
    }

    k_init<<<32, 512>>>();
    k_xwx<<<dim3(16, 128), 256>>>(x, cWx, cb);
    k_conv<<<dim3(T_ / 16, B_), 720>>>(x, c1w, c1b, c2w, c2b, c3w, c3b);
    k_revxw<<<T_, 320>>>(x, rWx);
    k_revscan<<<1, 320>>>(rWh, rb);
    k_gate<<<(T_ * B_) / 8, 128>>>(x, d0W, d0b, d1W, d1b, gn);
    k_scan<<<NBLK, 256, SMEM>>>(cWh, out);
}